// round 7
// baseline (speedup 1.0000x reference)
#include <cuda_runtime.h>
#include <cuda_bf16.h>
#include <math.h>

// ---- problem constants ----
#define NPTS   4096
#define NVIEW  6
#define SDIM   128
#define KTOP   5
#define RADIUS 0.01f
#define R2F    (RADIUS*RADIUS)
#define ZNEARF 0.01f
#define ZFARF  100.0f
#define NPIX   (NVIEW*SDIM*SDIM)   // 98304
#define MSLOT  16
#define TPB    256
#define BIGZ   3.0e38f

// ---- scratch (static __device__; zero-initialized at module load; the
// composite kernel resets g_cnt after reading it, so every invocation /
// graph replay starts from zeroed counters without a memset node).
// SoA, slot-major with stride NPIX: composite loads are fully coalesced
// (adjacent pixels -> adjacent addresses within one slot level). ----
__device__ int   g_cnt[NPIX];
__device__ float g_z[MSLOT*NPIX];
__device__ float g_w[MSLOT*NPIX];
__device__ float g_c[MSLOT*NPIX];

struct Cams {
    float R[NVIEW][9];   // row-major, columns are x,y,z camera basis
    float T[NVIEW][3];
};

// ---- kernel 1: one thread per (point, view); sigmoid fused in ----
__global__ void __launch_bounds__(TPB)
scatter_kernel(const float* __restrict__ pcd,
               const float* __restrict__ ic,
               const float* __restrict__ dp,
               float* __restrict__ out_tail,
               Cams cams) {
    int tid = blockIdx.x * TPB + threadIdx.x;
    if (tid >= NPTS * NVIEW) return;
    int i = tid & (NPTS - 1);      // point index (coalesced within a view group)
    int v = tid >> 12;             // view index (NPTS = 4096 = 2^12)

    float col = 1.0f / (1.0f + __expf(-(ic[i] + dp[i])));
    if (v == 0) out_tail[i] = col;             // colors_ tail of the output

    float p0 = pcd[3*i+0], p1 = pcd[3*i+1], p2 = pcd[3*i+2];
    const float* R = cams.R[v];
    const float* T = cams.T[v];
    float px = p0*R[0] + p1*R[3] + p2*R[6] + T[0];
    float py = p0*R[1] + p1*R[4] + p2*R[7] + T[1];
    float pz = p0*R[2] + p1*R[5] + p2*R[8] + T[2];
    if (!(pz > ZNEARF && pz < ZFARF)) return;

    // pixel center coord (col j / row r): (S-1-2j)/S.
    // candidate band |t-j| < S*R/2 = 0.64 (0.66 slack; exact d2<R2 test below)
    float tx = 0.5f * ((float)(SDIM-1) - (float)SDIM * px);
    float ty = 0.5f * ((float)(SDIM-1) - (float)SDIM * py);
    int jlo = (int)ceilf (tx - 0.66f); if (jlo < 0) jlo = 0;
    int jhi = (int)floorf(tx + 0.66f); if (jhi > SDIM-1) jhi = SDIM-1;
    int ilo = (int)ceilf (ty - 0.66f); if (ilo < 0) ilo = 0;
    int ihi = (int)floorf(ty + 0.66f); if (ihi > SDIM-1) ihi = SDIM-1;

    for (int r = ilo; r <= ihi; r++) {
        float dy = (float)(SDIM-1-2*r) * (1.0f/(float)SDIM) - py;
        float dy2 = dy * dy;
        for (int c = jlo; c <= jhi; c++) {
            float dx = (float)(SDIM-1-2*c) * (1.0f/(float)SDIM) - px;
            float d2 = dx*dx + dy2;
            if (d2 < R2F) {
                int pix = (v*SDIM + r)*SDIM + c;
                int n = atomicAdd(&g_cnt[pix], 1);
                if (n < MSLOT) {
                    int idx = n*NPIX + pix;
                    g_z[idx] = pz;
                    g_w[idx] = 1.0f - d2 * (1.0f/R2F);
                    g_c[idx] = col;
                }
            }
        }
    }
}

// ---- kernel 2: 1 thread/pixel; prefetched coalesced loads + register top-K ----
__global__ void __launch_bounds__(TPB)
composite_kernel(float* __restrict__ out) {
    int pix = blockIdx.x * TPB + threadIdx.x;
    if (pix >= NPIX) return;

    // All 7 loads independent -> issued back-to-back, one latency to cover.
    // Slots 0/1 may hold stale data from a previous replay; they are gated
    // by n below, so stale values are never consumed.
    int   n  = g_cnt[pix];
    float z0 = g_z[pix];         float z1 = g_z[NPIX + pix];
    float w0 = g_w[pix];         float w1 = g_w[NPIX + pix];
    float c0 = g_c[pix];         float c1 = g_c[NPIX + pix];
    g_cnt[pix] = 0;                      // leave counters zeroed for next replay
    if (n > MSLOT) n = MSLOT;

    float acc = 0.0f;
    if (n > 0) {
        // sorted-by-z register lists (ascending); branch-free insertion
        float bz[KTOP], bw[KTOP], bc[KTOP];
        #pragma unroll
        for (int k = 0; k < KTOP; k++) { bz[k] = BIGZ; bw[k] = 0.0f; bc[k] = 0.0f; }

        // insert slot 0 (always valid when n>0)
        bz[0] = z0; bw[0] = w0; bc[0] = c0;

        if (n > 1) {
            // insert slot 1
            {
                float z = z1, w = w1, c = c1;
                #pragma unroll
                for (int k = 0; k < KTOP; k++) {
                    bool sw = z < bz[k];
                    float tz = bz[k], tw = bw[k], tc = bc[k];
                    if (sw) { bz[k] = z; bw[k] = w; bc[k] = c; z = tz; w = tw; c = tc; }
                }
            }
            // rare tail (P(n>2) ~ 0.5%): remaining slots, coalesced per level
            for (int e = 2; e < n; e++) {
                int idx = e*NPIX + pix;
                float z = g_z[idx], w = g_w[idx], c = g_c[idx];
                #pragma unroll
                for (int k = 0; k < KTOP; k++) {
                    bool sw = z < bz[k];
                    float tz = bz[k], tw = bw[k], tc = bc[k];
                    if (sw) { bz[k] = z; bw[k] = w; bc[k] = c; z = tz; w = tw; c = tc; }
                }
            }
        }

        float trans = 1.0f;
        #pragma unroll
        for (int k = 0; k < KTOP; k++) {
            bool ok = bz[k] < BIGZ;
            float w = ok ? bw[k] : 0.0f;
            acc  += w * trans * bc[k];
            trans *= (1.0f - w);
        }
    }

    float* o = out + (size_t)pix * 3;
    o[0] = acc; o[1] = acc; o[2] = acc;
}

// ---- host: replicate PyTorch3D look_at_view_transform ----
static void compute_cams(Cams& cams) {
    const double views[NVIEW] = {45.0, 90.0, 135.0, 225.0, 270.0, 315.0};
    const double elev = 15.0 * M_PI / 180.0;
    const double dist = 1.5;
    for (int v = 0; v < NVIEW; v++) {
        double az = views[v] * M_PI / 180.0;
        double C[3] = { dist*cos(elev)*sin(az), dist*sin(elev), dist*cos(elev)*cos(az) };
        double z[3] = { -C[0]/dist, -C[1]/dist, -C[2]/dist };
        double x[3] = { z[2], 0.0, -z[0] };
        double xn = sqrt(x[0]*x[0] + x[1]*x[1] + x[2]*x[2]);
        x[0]/=xn; x[1]/=xn; x[2]/=xn;
        double y[3] = { z[1]*x[2]-z[2]*x[1], z[2]*x[0]-z[0]*x[2], z[0]*x[1]-z[1]*x[0] };
        double yn = sqrt(y[0]*y[0] + y[1]*y[1] + y[2]*y[2]);
        y[0]/=yn; y[1]/=yn; y[2]/=yn;
        for (int r = 0; r < 3; r++) {
            cams.R[v][r*3+0] = (float)x[r];
            cams.R[v][r*3+1] = (float)y[r];
            cams.R[v][r*3+2] = (float)z[r];
        }
        cams.T[v][0] = (float)(-(C[0]*x[0] + C[1]*x[1] + C[2]*x[2]));
        cams.T[v][1] = (float)(-(C[0]*y[0] + C[1]*y[1] + C[2]*y[2]));
        cams.T[v][2] = (float)(-(C[0]*z[0] + C[1]*z[1] + C[2]*z[2]));
    }
}

extern "C" void kernel_launch(void* const* d_in, const int* in_sizes, int n_in,
                              void* d_out, int out_size) {
    const float* pcd = (const float*)d_in[0];
    const float* ic  = (const float*)d_in[1];
    const float* dp  = (const float*)d_in[2];
    float* out = (float*)d_out;

    Cams cams;
    compute_cams(cams);

    scatter_kernel<<<(NPTS*NVIEW + TPB-1) / TPB, TPB>>>(pcd, ic, dp,
                                                        out + (size_t)NPIX*3, cams);
    composite_kernel<<<(NPIX + TPB-1) / TPB, TPB>>>(out);
}

// round 8
// speedup vs baseline: 1.0025x; 1.0025x over previous
#include <cuda_runtime.h>
#include <cuda_bf16.h>
#include <math.h>

// ---- problem constants ----
#define NPTS   4096
#define NVIEW  6
#define SDIM   128
#define KTOP   5
#define RADIUS 0.01f
#define R2F    (RADIUS*RADIUS)
#define ZNEARF 0.01f
#define ZFARF  100.0f
#define NPIX   (NVIEW*SDIM*SDIM)   // 98304
#define MSLOT  16
#define TPB    256
#define BIGZ   3.0e38f

// ---- scratch (static __device__; zero-initialized at module load; the
// composite kernel resets g_cnt after reading it, so every invocation /
// graph replay starts from zeroed counters without a memset node).
// SoA, slot-major with stride NPIX: composite loads fully coalesced. ----
__device__ int   g_cnt[NPIX];
__device__ float g_z[MSLOT*NPIX];
__device__ float g_w[MSLOT*NPIX];
__device__ float g_c[MSLOT*NPIX];

struct Cams {
    float R[NVIEW][9];   // row-major, columns are x,y,z camera basis
    float T[NVIEW][3];
};

// ---- kernel 1: one thread per (point, view); sigmoid fused in.
// NOTE: does NOT call cudaTriggerProgrammaticLaunchCompletion() — the PDL
// completion fires implicitly at kernel exit, which guarantees all scatter
// writes are visible to the dependent composite kernel after its gridsync.
__global__ void __launch_bounds__(TPB)
scatter_kernel(const float* __restrict__ pcd,
               const float* __restrict__ ic,
               const float* __restrict__ dp,
               float* __restrict__ out_tail,
               Cams cams) {
    int tid = blockIdx.x * TPB + threadIdx.x;
    if (tid >= NPTS * NVIEW) return;
    int i = tid & (NPTS - 1);      // point index (coalesced within a view group)
    int v = tid >> 12;             // view index (NPTS = 4096 = 2^12)

    float col = 1.0f / (1.0f + __expf(-(ic[i] + dp[i])));
    if (v == 0) out_tail[i] = col;             // colors_ tail of the output

    float p0 = pcd[3*i+0], p1 = pcd[3*i+1], p2 = pcd[3*i+2];
    const float* R = cams.R[v];
    const float* T = cams.T[v];
    float px = p0*R[0] + p1*R[3] + p2*R[6] + T[0];
    float py = p0*R[1] + p1*R[4] + p2*R[7] + T[1];
    float pz = p0*R[2] + p1*R[5] + p2*R[8] + T[2];
    if (!(pz > ZNEARF && pz < ZFARF)) return;

    // pixel center coord (col j / row r): (S-1-2j)/S.
    // candidate band |t-j| < S*R/2 = 0.64 (0.66 slack; exact d2<R2 test below)
    float tx = 0.5f * ((float)(SDIM-1) - (float)SDIM * px);
    float ty = 0.5f * ((float)(SDIM-1) - (float)SDIM * py);
    int jlo = (int)ceilf (tx - 0.66f); if (jlo < 0) jlo = 0;
    int jhi = (int)floorf(tx + 0.66f); if (jhi > SDIM-1) jhi = SDIM-1;
    int ilo = (int)ceilf (ty - 0.66f); if (ilo < 0) ilo = 0;
    int ihi = (int)floorf(ty + 0.66f); if (ihi > SDIM-1) ihi = SDIM-1;

    for (int r = ilo; r <= ihi; r++) {
        float dy = (float)(SDIM-1-2*r) * (1.0f/(float)SDIM) - py;
        float dy2 = dy * dy;
        for (int c = jlo; c <= jhi; c++) {
            float dx = (float)(SDIM-1-2*c) * (1.0f/(float)SDIM) - px;
            float d2 = dx*dx + dy2;
            if (d2 < R2F) {
                int pix = (v*SDIM + r)*SDIM + c;
                int n = atomicAdd(&g_cnt[pix], 1);
                if (n < MSLOT) {
                    int idx = n*NPIX + pix;
                    g_z[idx] = pz;
                    g_w[idx] = 1.0f - d2 * (1.0f/R2F);
                    g_c[idx] = col;
                }
            }
        }
    }
}

// ---- kernel 2: PDL secondary. Blocks launch while scatter runs; gridsync
// waits for scatter completion (and write visibility), skipping a launch ramp. ----
__global__ void __launch_bounds__(TPB)
composite_kernel(float* __restrict__ out) {
    int pix = blockIdx.x * TPB + threadIdx.x;

#if __CUDA_ARCH__ >= 900
    cudaGridDependencySynchronize();
#endif

    if (pix >= NPIX) return;

    // 4 independent loads issued back-to-back; slot 0 may be stale from a
    // previous replay but is gated by n below.
    int   n  = g_cnt[pix];
    float z0 = g_z[pix];
    float w0 = g_w[pix];
    float c0 = g_c[pix];
    g_cnt[pix] = 0;                      // leave counters zeroed for next replay
    if (n > MSLOT) n = MSLOT;

    float acc = 0.0f;
    if (n > 0) {
        // sorted-by-z register lists (ascending); branch-free insertion
        float bz[KTOP], bw[KTOP], bc[KTOP];
        #pragma unroll
        for (int k = 0; k < KTOP; k++) { bz[k] = BIGZ; bw[k] = 0.0f; bc[k] = 0.0f; }

        bz[0] = z0; bw[0] = w0; bc[0] = c0;   // slot 0 always valid when n>0

        // rare tail (P(n>=2) ~ 4.5%): remaining slots, coalesced per level
        for (int e = 1; e < n; e++) {
            int idx = e*NPIX + pix;
            float z = g_z[idx], w = g_w[idx], c = g_c[idx];
            #pragma unroll
            for (int k = 0; k < KTOP; k++) {
                bool sw = z < bz[k];
                float tz = bz[k], tw = bw[k], tc = bc[k];
                if (sw) { bz[k] = z; bw[k] = w; bc[k] = c; z = tz; w = tw; c = tc; }
            }
        }

        float trans = 1.0f;
        #pragma unroll
        for (int k = 0; k < KTOP; k++) {
            bool ok = bz[k] < BIGZ;
            float w = ok ? bw[k] : 0.0f;
            acc  += w * trans * bc[k];
            trans *= (1.0f - w);
        }
    }

    float* o = out + (size_t)pix * 3;
    o[0] = acc; o[1] = acc; o[2] = acc;
}

// ---- host: replicate PyTorch3D look_at_view_transform ----
static void compute_cams(Cams& cams) {
    const double views[NVIEW] = {45.0, 90.0, 135.0, 225.0, 270.0, 315.0};
    const double elev = 15.0 * M_PI / 180.0;
    const double dist = 1.5;
    for (int v = 0; v < NVIEW; v++) {
        double az = views[v] * M_PI / 180.0;
        double C[3] = { dist*cos(elev)*sin(az), dist*sin(elev), dist*cos(elev)*cos(az) };
        double z[3] = { -C[0]/dist, -C[1]/dist, -C[2]/dist };
        double x[3] = { z[2], 0.0, -z[0] };
        double xn = sqrt(x[0]*x[0] + x[1]*x[1] + x[2]*x[2]);
        x[0]/=xn; x[1]/=xn; x[2]/=xn;
        double y[3] = { z[1]*x[2]-z[2]*x[1], z[2]*x[0]-z[0]*x[2], z[0]*x[1]-z[1]*x[0] };
        double yn = sqrt(y[0]*y[0] + y[1]*y[1] + y[2]*y[2]);
        y[0]/=yn; y[1]/=yn; y[2]/=yn;
        for (int r = 0; r < 3; r++) {
            cams.R[v][r*3+0] = (float)x[r];
            cams.R[v][r*3+1] = (float)y[r];
            cams.R[v][r*3+2] = (float)z[r];
        }
        cams.T[v][0] = (float)(-(C[0]*x[0] + C[1]*x[1] + C[2]*x[2]));
        cams.T[v][1] = (float)(-(C[0]*y[0] + C[1]*y[1] + C[2]*y[2]));
        cams.T[v][2] = (float)(-(C[0]*z[0] + C[1]*z[1] + C[2]*z[2]));
    }
}

extern "C" void kernel_launch(void* const* d_in, const int* in_sizes, int n_in,
                              void* d_out, int out_size) {
    const float* pcd = (const float*)d_in[0];
    const float* ic  = (const float*)d_in[1];
    const float* dp  = (const float*)d_in[2];
    float* out = (float*)d_out;

    Cams cams;
    compute_cams(cams);

    scatter_kernel<<<(NPTS*NVIEW + TPB-1) / TPB, TPB>>>(pcd, ic, dp,
                                                        out + (size_t)NPIX*3, cams);

    // Composite as a Programmatic Dependent Launch: its blocks get dispatched
    // while scatter is still running; gridsync inside provides the ordering.
    cudaLaunchConfig_t cfg = {};
    cfg.gridDim  = dim3((NPIX + TPB - 1) / TPB);
    cfg.blockDim = dim3(TPB);
    cfg.dynamicSmemBytes = 0;
    cfg.stream = 0;
    cudaLaunchAttribute attrs[1];
    attrs[0].id = cudaLaunchAttributeProgrammaticStreamSerialization;
    attrs[0].val.programmaticStreamSerializationAllowed = 1;
    cfg.attrs = attrs;
    cfg.numAttrs = 1;
    cudaLaunchKernelEx(&cfg, composite_kernel, out);
}

// round 9
// speedup vs baseline: 1.1940x; 1.1910x over previous
#include <cuda_runtime.h>
#include <cuda_bf16.h>
#include <math.h>

// ---- problem constants ----
#define NPTS   4096
#define NVIEW  6
#define SDIM   128
#define KTOP   5
#define RADIUS 0.01f
#define R2F    (RADIUS*RADIUS)
#define ZNEARF 0.01f
#define ZFARF  100.0f
#define NPIX   (NVIEW*SDIM*SDIM)   // 98304
#define MSLOT  16
#define TPB    256
#define BIGZ   3.0e38f

// ---- scratch (static __device__; zero-initialized at module load; the
// composite kernel resets g_cnt after reading it, so every replay starts
// from zeroed counters without a memset node).
// Entries are float4 (z, w, c, pad), SLOT-MAJOR: g_e[slot*NPIX + pix].
// -> composite: one coalesced LDG.128 per slot level per thread
// -> scatter:   one STG.128 per hit ----
__device__ int    g_cnt[NPIX];
__device__ float4 g_e[MSLOT*NPIX];

struct Cams {
    float R[NVIEW][9];   // row-major, columns are x,y,z camera basis
    float T[NVIEW][3];
};

// ---- kernel 1: one thread per (point, view); sigmoid fused in ----
__global__ void __launch_bounds__(TPB)
scatter_kernel(const float* __restrict__ pcd,
               const float* __restrict__ ic,
               const float* __restrict__ dp,
               float* __restrict__ out_tail,
               Cams cams) {
    int tid = blockIdx.x * TPB + threadIdx.x;
    if (tid >= NPTS * NVIEW) return;
    int i = tid & (NPTS - 1);      // point index (coalesced within a view group)
    int v = tid >> 12;             // view index (NPTS = 4096 = 2^12)

    float col = 1.0f / (1.0f + __expf(-(ic[i] + dp[i])));
    if (v == 0) out_tail[i] = col;             // colors_ tail of the output

    float p0 = pcd[3*i+0], p1 = pcd[3*i+1], p2 = pcd[3*i+2];
    const float* R = cams.R[v];
    const float* T = cams.T[v];
    float px = p0*R[0] + p1*R[3] + p2*R[6] + T[0];
    float py = p0*R[1] + p1*R[4] + p2*R[7] + T[1];
    float pz = p0*R[2] + p1*R[5] + p2*R[8] + T[2];
    if (!(pz > ZNEARF && pz < ZFARF)) return;

    // pixel center coord (col j / row r): (S-1-2j)/S.
    // candidate band |t-j| < S*R/2 = 0.64 (0.66 slack; exact d2<R2 test below)
    float tx = 0.5f * ((float)(SDIM-1) - (float)SDIM * px);
    float ty = 0.5f * ((float)(SDIM-1) - (float)SDIM * py);
    int jlo = (int)ceilf (tx - 0.66f); if (jlo < 0) jlo = 0;
    int jhi = (int)floorf(tx + 0.66f); if (jhi > SDIM-1) jhi = SDIM-1;
    int ilo = (int)ceilf (ty - 0.66f); if (ilo < 0) ilo = 0;
    int ihi = (int)floorf(ty + 0.66f); if (ihi > SDIM-1) ihi = SDIM-1;

    for (int r = ilo; r <= ihi; r++) {
        float dy = (float)(SDIM-1-2*r) * (1.0f/(float)SDIM) - py;
        float dy2 = dy * dy;
        for (int c = jlo; c <= jhi; c++) {
            float dx = (float)(SDIM-1-2*c) * (1.0f/(float)SDIM) - px;
            float d2 = dx*dx + dy2;
            if (d2 < R2F) {
                int pix = (v*SDIM + r)*SDIM + c;
                int n = atomicAdd(&g_cnt[pix], 1);
                if (n < MSLOT) {
                    g_e[n*NPIX + pix] =
                        make_float4(pz, 1.0f - d2 * (1.0f/R2F), col, 0.0f);
                }
            }
        }
    }
}

// branch-free insertion of (z,w,c) into ascending-by-z register lists
__device__ __forceinline__ void insert5(float z, float w, float c,
                                        float (&bz)[KTOP], float (&bw)[KTOP],
                                        float (&bc)[KTOP]) {
    #pragma unroll
    for (int k = 0; k < KTOP; k++) {
        bool sw = z < bz[k];
        float tz = bz[k], tw = bw[k], tc = bc[k];
        if (sw) { bz[k] = z; bw[k] = w; bc[k] = c; z = tz; w = tw; c = tc; }
    }
}

// ---- kernel 2: PDL secondary; 1 thread/pixel; uniform 3-slot prefetch ----
__global__ void __launch_bounds__(TPB)
composite_kernel(float* __restrict__ out) {
    int pix = blockIdx.x * TPB + threadIdx.x;

#if __CUDA_ARCH__ >= 900
    cudaGridDependencySynchronize();
#endif

    if (pix >= NPIX) return;

    // cnt + 3 slot entries: 4 independent loads issued back-to-back.
    // Slots may hold stale data from a previous replay; gated by n below.
    int    n  = g_cnt[pix];
    float4 e0 = g_e[pix];
    float4 e1 = g_e[NPIX   + pix];
    float4 e2 = g_e[2*NPIX + pix];
    g_cnt[pix] = 0;                      // leave counters zeroed for next replay
    if (n > MSLOT) n = MSLOT;

    float acc = 0.0f;
    if (n > 0) {
        float bz[KTOP], bw[KTOP], bc[KTOP];
        #pragma unroll
        for (int k = 0; k < KTOP; k++) { bz[k] = BIGZ; bw[k] = 0.0f; bc[k] = 0.0f; }

        bz[0] = e0.x; bw[0] = e0.y; bc[0] = e0.z;          // slot 0 always valid
        if (n > 1) insert5(e1.x, e1.y, e1.z, bz, bw, bc);  // predicated, uniform
        if (n > 2) insert5(e2.x, e2.y, e2.z, bz, bw, bc);

        // very rare tail (P(warp has any n>3) < ~2%)
        for (int e = 3; e < n; e++) {
            float4 ee = g_e[e*NPIX + pix];
            insert5(ee.x, ee.y, ee.z, bz, bw, bc);
        }

        float trans = 1.0f;
        #pragma unroll
        for (int k = 0; k < KTOP; k++) {
            bool ok = bz[k] < BIGZ;
            float w = ok ? bw[k] : 0.0f;
            acc  += w * trans * bc[k];
            trans *= (1.0f - w);
        }
    }

    float* o = out + (size_t)pix * 3;
    o[0] = acc; o[1] = acc; o[2] = acc;
}

// ---- host: replicate PyTorch3D look_at_view_transform ----
static void compute_cams(Cams& cams) {
    const double views[NVIEW] = {45.0, 90.0, 135.0, 225.0, 270.0, 315.0};
    const double elev = 15.0 * M_PI / 180.0;
    const double dist = 1.5;
    for (int v = 0; v < NVIEW; v++) {
        double az = views[v] * M_PI / 180.0;
        double C[3] = { dist*cos(elev)*sin(az), dist*sin(elev), dist*cos(elev)*cos(az) };
        double z[3] = { -C[0]/dist, -C[1]/dist, -C[2]/dist };
        double x[3] = { z[2], 0.0, -z[0] };
        double xn = sqrt(x[0]*x[0] + x[1]*x[1] + x[2]*x[2]);
        x[0]/=xn; x[1]/=xn; x[2]/=xn;
        double y[3] = { z[1]*x[2]-z[2]*x[1], z[2]*x[0]-z[0]*x[2], z[0]*x[1]-z[1]*x[0] };
        double yn = sqrt(y[0]*y[0] + y[1]*y[1] + y[2]*y[2]);
        y[0]/=yn; y[1]/=yn; y[2]/=yn;
        for (int r = 0; r < 3; r++) {
            cams.R[v][r*3+0] = (float)x[r];
            cams.R[v][r*3+1] = (float)y[r];
            cams.R[v][r*3+2] = (float)z[r];
        }
        cams.T[v][0] = (float)(-(C[0]*x[0] + C[1]*x[1] + C[2]*x[2]));
        cams.T[v][1] = (float)(-(C[0]*y[0] + C[1]*y[1] + C[2]*y[2]));
        cams.T[v][2] = (float)(-(C[0]*z[0] + C[1]*z[1] + C[2]*z[2]));
    }
}

extern "C" void kernel_launch(void* const* d_in, const int* in_sizes, int n_in,
                              void* d_out, int out_size) {
    const float* pcd = (const float*)d_in[0];
    const float* ic  = (const float*)d_in[1];
    const float* dp  = (const float*)d_in[2];
    float* out = (float*)d_out;

    Cams cams;
    compute_cams(cams);

    scatter_kernel<<<(NPTS*NVIEW + TPB-1) / TPB, TPB>>>(pcd, ic, dp,
                                                        out + (size_t)NPIX*3, cams);

    // Composite as a Programmatic Dependent Launch (free overlap of its
    // dispatch with scatter execution; gridsync provides ordering).
    cudaLaunchConfig_t cfg = {};
    cfg.gridDim  = dim3((NPIX + TPB - 1) / TPB);
    cfg.blockDim = dim3(TPB);
    cfg.dynamicSmemBytes = 0;
    cfg.stream = 0;
    cudaLaunchAttribute attrs[1];
    attrs[0].id = cudaLaunchAttributeProgrammaticStreamSerialization;
    attrs[0].val.programmaticStreamSerializationAllowed = 1;
    cfg.attrs = attrs;
    cfg.numAttrs = 1;
    cudaLaunchKernelEx(&cfg, composite_kernel, out);
}